// round 15
// baseline (speedup 1.0000x reference)
#include <cuda_runtime.h>
#include <cstdint>

// RNN: B=512, T=512, D=64, H=512, O=1
// R9: cluster k-split (2 CTAs) + 4 k-groups x 128 thr (512 thr).
//  Acc layout: col-pairs per row -> w loads naturally paired (no pack MOVs).
//  h stored DUPLICATED in smem as u64 {h,h}, layout [row][j] (one LDS.128
//  broadcast covers 2 k-steps). UPF=8 streamed prefetch. Push-based DSMEM
//  exchange (st.shared::cluster), local reads after cluster.sync.

#define BSZ 512
#define TSZ 512
#define DSZ 64
#define HSZ 512
#define KH  256
#define CROWS 8
#define NTHR 512
#define NCTA 128
#define NG   4
#define KG   64
#define KCG  16
#define UPF  8        // (KG-KCG)=48, 48%8==0

// smem floats: whc 4*16*512=32768 | hdup 8*256*2=4096 | xbf 2*8*64*4=4096
//              red 3*8*128*4=12288 | wd 512  -> 53760 f = 215040 B
#define SMEM_MAIN_BYTES ((NG*KCG*HSZ + 8*256*2 + 2*8*64*4 + 3*8*128*4 + 512) * 4)

#define TT 16
#define NTHRX 256
#define SMEM_XW_BYTES ((DSZ * HSZ + TT * DSZ * 4) * 4)

__device__ float g_xw[(size_t)TSZ * BSZ * HSZ];   // [T][B][H]

typedef unsigned long long u64;

__device__ __forceinline__ void ffma2(u64& acc, u64 a, u64 b) {
    asm("fma.rn.f32x2 %0, %1, %2, %0;" : "+l"(acc) : "l"(a), "l"(b));
}
__device__ __forceinline__ u64 pack2(float lo, float hi) {
    u64 r; asm("mov.b64 %0, {%1, %2};" : "=l"(r) : "f"(lo), "f"(hi)); return r;
}
__device__ __forceinline__ void unpack2(float& lo, float& hi, u64 v) {
    asm("mov.b64 {%0, %1}, %2;" : "=f"(lo), "=f"(hi) : "l"(v));
}
__device__ __forceinline__ float4 u64pair_f4(u64 a, u64 b) {
    float4 v;
    unpack2(v.x, v.y, a);
    unpack2(v.z, v.w, b);
    return v;
}
__device__ __forceinline__ uint32_t smem_u32(const void* p) {
    uint32_t a;
    asm("{ .reg .u64 t; cvta.to.shared.u64 t, %1; cvt.u32.u64 %0, t; }"
        : "=r"(a) : "l"(p));
    return a;
}
__device__ __forceinline__ uint32_t mapa_peer(uint32_t addr, uint32_t peer) {
    uint32_t r;
    asm("mapa.shared::cluster.u32 %0, %1, %2;" : "=r"(r) : "r"(addr), "r"(peer));
    return r;
}
__device__ __forceinline__ void st_cluster_f4(uint32_t a, float4 v) {
    asm volatile("st.shared::cluster.v4.f32 [%0], {%1,%2,%3,%4};"
                 :: "r"(a), "f"(v.x), "f"(v.y), "f"(v.z), "f"(v.w) : "memory");
}
__device__ __forceinline__ void st_cluster_f32(uint32_t a, float v) {
    asm volatile("st.shared::cluster.f32 [%0], %1;" :: "r"(a), "f"(v) : "memory");
}
#define CLUSTER_SYNC() do { \
    asm volatile("barrier.cluster.arrive.aligned;" ::: "memory"); \
    asm volatile("barrier.cluster.wait.aligned;"   ::: "memory"); \
} while (0)

// two k-steps for all 8 rows: w0,w1 = {wc01},{wc23} for k,k+1; hv = {h(r,k),h(r,k+1)} dup'd
__device__ __forceinline__ void step2(u64 A[8][2], ulonglong2 w0, ulonglong2 w1,
                                      const u64* hk, int kk) {
    #pragma unroll
    for (int r = 0; r < 8; r++) {
        ulonglong2 hv = *reinterpret_cast<const ulonglong2*>(hk + r * 256 + kk);
        ffma2(A[r][0], w0.x, hv.x);
        ffma2(A[r][1], w0.y, hv.x);
        ffma2(A[r][0], w1.x, hv.y);
        ffma2(A[r][1], w1.y, hv.y);
    }
}

// ---------------------------------------------------------------------------
// Kernel 1: XW = x @ W_x + b_rnn   (unchanged)
// ---------------------------------------------------------------------------
__global__ __launch_bounds__(NTHRX, 1)
void xw_kernel(const float* __restrict__ x,
               const float* __restrict__ Wx,
               const float* __restrict__ brnn)
{
    extern __shared__ float smem[];
    float* wx_s = smem;
    float* xs   = wx_s + DSZ * HSZ;

    const int tid = threadIdx.x;
    const int t0  = blockIdx.x * TT;
    const int b0  = blockIdx.y * 4;

    {
        const float4* g = reinterpret_cast<const float4*>(Wx);
        float4* d = reinterpret_cast<float4*>(wx_s);
        #pragma unroll 8
        for (int i = tid; i < DSZ * HSZ / 4; i += NTHRX) d[i] = g[i];
    }
    #pragma unroll
    for (int i = 0; i < TT * DSZ * 4 / NTHRX; i++) {
        int idx = tid + i * NTHRX;
        int d = idx & 63;
        int t = (idx >> 6) & (TT - 1);
        int r = idx >> 10;
        xs[(t * DSZ + d) * 4 + r] = x[((size_t)(b0 + r) * TSZ + t0 + t) * DSZ + d];
    }
    __syncthreads();

    const float2* wx2 = reinterpret_cast<const float2*>(wx_s) + tid;
    float bA = brnn[2 * tid], bB = brnn[2 * tid + 1];
    u64 bA2 = pack2(bA, bA), bB2 = pack2(bB, bB);

    float2* xwo = reinterpret_cast<float2*>(g_xw);

    for (int t = 0; t < TT; t++) {
        u64 a01 = bA2, a23 = bA2, c01 = bB2, c23 = bB2;
        const ulonglong2* xv = reinterpret_cast<const ulonglong2*>(xs + t * DSZ * 4);
        #pragma unroll 8
        for (int k = 0; k < DSZ; k++) {
            float2 w = wx2[k * (HSZ / 2)];
            ulonglong2 hv = xv[k];
            u64 wA = pack2(w.x, w.x);
            u64 wB = pack2(w.y, w.y);
            ffma2(a01, wA, hv.x);
            ffma2(a23, wA, hv.y);
            ffma2(c01, wB, hv.x);
            ffma2(c23, wB, hv.y);
        }
        float a0, a1, a2, a3, c0, c1, c2, c3;
        unpack2(a0, a1, a01); unpack2(a2, a3, a23);
        unpack2(c0, c1, c01); unpack2(c2, c3, c23);
        size_t base = ((size_t)(t0 + t) * BSZ + b0) * (HSZ / 2) + tid;
        xwo[base]                 = make_float2(a0, c0);
        xwo[base + (HSZ / 2)]     = make_float2(a1, c1);
        xwo[base + 2 * (HSZ / 2)] = make_float2(a2, c2);
        xwo[base + 3 * (HSZ / 2)] = make_float2(a3, c3);
    }
}

// ---------------------------------------------------------------------------
// Kernel 2: clustered persistent recurrence.
// ---------------------------------------------------------------------------
__global__ __launch_bounds__(NTHR, 1) __cluster_dims__(2, 1, 1)
void rnn_cluster_kernel(const float* __restrict__ Wh,
                        const float* __restrict__ Wd,
                        const float* __restrict__ bd,
                        float* __restrict__ out)
{
    extern __shared__ float smem[];
    float*  whc  = smem;                                    // [NG][KCG][512]
    u64*    hdup = reinterpret_cast<u64*>(whc + NG * KCG * HSZ);  // [8][256] {h,h}
    float4* xbf4 = reinterpret_cast<float4*>(hdup + 8 * 256);     // [2][8][64]
    float4* red4 = xbf4 + 2 * 8 * 64;                       // [3*8][128]
    float*  wd_s = reinterpret_cast<float*>(red4 + 24 * 128);     // [512]

    const int tid = threadIdx.x;
    uint32_t rank;
    asm("mov.u32 %0, %%cluster_ctarank;" : "=r"(rank));
    const uint32_t peer = rank ^ 1u;
    const int b0 = (blockIdx.x >> 1) * CROWS;
    const int g  = tid >> 7;            // k-group 0..3
    const int lq = tid & 127;           // col-quad: cols 4lq..4lq+3
    const bool g0  = (g == 0);
    const bool own = g0 && ((lq >> 6) == (int)rank);
    const int  s6  = lq & 63;

    // ---- preload cached W_h rows (per group) and W_d ----
    {
        #pragma unroll
        for (int gg = 0; gg < NG; gg++) {
            const float4* src = reinterpret_cast<const float4*>(
                Wh + ((size_t)rank * KH + gg * KG) * HSZ);
            float4* dst = reinterpret_cast<float4*>(whc + gg * KCG * HSZ);
            #pragma unroll 2
            for (int i = tid; i < KCG * HSZ / 4; i += NTHR) dst[i] = src[i];
        }
        wd_s[tid & 511] = Wd[tid & 511];
    }
    __syncthreads();

    const ulonglong2* wcp = reinterpret_cast<const ulonglong2*>(whc + g * KCG * HSZ) + lq;
    const ulonglong2* wgp = reinterpret_cast<const ulonglong2*>(Wh)
                            + ((size_t)(rank * KH + g * KG + KCG)) * (HSZ / 4) + lq;
    const u64*    hk  = hdup + g * KG;           // + r*256 + k
    const float4* xw4 = reinterpret_cast<const float4*>(g_xw);
    const uint32_t xb_base = smem_u32(xbf4);

    for (int t = 0; t < TSZ; t++) {
        const int p = t & 1;

        u64 A[8][2];
        #pragma unroll
        for (int r = 0; r < 8; r++) { A[r][0] = 0ull; A[r][1] = 0ull; }

        if (t > 0) {
            // ---- cached rows ----
            #pragma unroll
            for (int k = 0; k < KCG; k += 2) {
                ulonglong2 w0 = wcp[k * (HSZ / 4)];
                ulonglong2 w1 = wcp[(k + 1) * (HSZ / 4)];
                step2(A, w0, w1, hk, k);
            }
            // ---- streamed rows, UPF-deep rotating prefetch ----
            ulonglong2 wreg[UPF];
            #pragma unroll
            for (int u = 0; u < UPF; u++)
                wreg[u] = wgp[u * (HSZ / 4)];

            for (int kb = KCG; kb < KG; kb += UPF) {
                #pragma unroll
                for (int u = 0; u < UPF; u += 2) {
                    ulonglong2 w0 = wreg[u], w1 = wreg[u + 1];
                    if (kb + UPF < KG) {
                        wreg[u]     = wgp[(size_t)(kb - KCG + UPF + u) * (HSZ / 4)];
                        wreg[u + 1] = wgp[(size_t)(kb - KCG + UPF + u + 1) * (HSZ / 4)];
                    }
                    step2(A, w0, w1, hk, kb + u);
                }
            }
        }

        // xw loads for our 8 rows (own only), overlapped with epilogue
        float4 xr[CROWS];
        if (own) {
            #pragma unroll
            for (int r = 0; r < CROWS; r++)
                xr[r] = xw4[((size_t)t * BSZ + b0 + r) * (HSZ / 4) + lq];
        }

        // ---- groups 1-3 -> scratch (float4 = 4 cols of one row) ----
        if (!g0) {
            #pragma unroll
            for (int r = 0; r < 8; r++)
                red4[((g - 1) * 8 + r) * 128 + lq] = u64pair_f4(A[r][0], A[r][1]);
        }
        __syncthreads();   // S1: red visible; all hdup reads drained

        float4 F[8];
        if (g0) {
            #pragma unroll
            for (int r = 0; r < 8; r++) {
                float4 f = u64pair_f4(A[r][0], A[r][1]);
                #pragma unroll
                for (int gg = 0; gg < 3; gg++) {
                    float4 q = red4[(gg * 8 + r) * 128 + lq];
                    f.x += q.x; f.y += q.y; f.z += q.z; f.w += q.w;
                }
                F[r] = f;
            }
            if (!own) {
                // push foreign partials straight into peer's xbf
                #pragma unroll
                for (int r = 0; r < 8; r++) {
                    uint32_t pa = mapa_peer(
                        xb_base + (uint32_t)((p * 8 + r) * 64 + s6) * 16, peer);
                    st_cluster_f4(pa, F[r]);
                }
            }
        }

        CLUSTER_SYNC();   // pushes visible; both CTAs' hdup reads done

        if (own) {
            #pragma unroll
            for (int r = 0; r < 8; r++) {
                float4 q = xbf4[(p * 8 + r) * 64 + s6];   // local read
                float4 f = F[r];
                f.x = fmaxf(f.x + q.x + xr[r].x, 0.f);
                f.y = fmaxf(f.y + q.y + xr[r].y, 0.f);
                f.z = fmaxf(f.z + q.z + xr[r].z, 0.f);
                f.w = fmaxf(f.w + q.w + xr[r].w, 0.f);
                // write duplicated h: element (r, j) = {h,h}, j = 4*s6+c
                u64* dst = hdup + r * 256 + 4 * s6;
                *reinterpret_cast<float4*>(dst)     = make_float4(f.x, f.x, f.y, f.y);
                *reinterpret_cast<float4*>(dst + 2) = make_float4(f.z, f.z, f.w, f.w);
            }
        }
        __syncthreads();   // S2: h_t visible CTA-wide
    }

    // ---- final dense: out[b] = relu(h_T[b,:] @ W_d + b_d) ----
    {
        const float* hf = reinterpret_cast<const float*>(hdup);
        float s = 0.f;
        if (tid < 256) {
            const int wr = tid >> 5;      // warp 0..7 -> batch row
            const int l  = tid & 31;
            #pragma unroll
            for (int i = 0; i < 8; i++) {
                int jl = l * 8 + i;
                s += hf[(wr * 256 + jl) * 2] * wd_s[rank * KH + jl];
            }
            #pragma unroll
            for (int off = 16; off > 0; off >>= 1)
                s += __shfl_xor_sync(0xffffffffu, s, off);
            if (rank == 1 && l == 0) {
                // push partial to peer's xbf
                st_cluster_f32(mapa_peer(xb_base + (uint32_t)wr * 4, peer), s);
            }
        }
        CLUSTER_SYNC();
        if (rank == 0 && tid < 256 && (tid & 31) == 0) {
            int wr = tid >> 5;
            float sp = reinterpret_cast<const float*>(xbf4)[wr];   // local read
            out[b0 + wr] = fmaxf(s + sp + bd[0], 0.f);
        }
        CLUSTER_SYNC();
    }
}

extern "C" void kernel_launch(void* const* d_in, const int* in_sizes, int n_in,
                              void* d_out, int out_size) {
    const float* x    = (const float*)d_in[0];
    const float* Wx   = (const float*)d_in[1];
    const float* Wh   = (const float*)d_in[2];
    const float* brnn = (const float*)d_in[3];
    const float* Wd   = (const float*)d_in[4];
    const float* bd   = (const float*)d_in[5];
    float* out = (float*)d_out;

    cudaFuncSetAttribute(xw_kernel,
                         cudaFuncAttributeMaxDynamicSharedMemorySize, SMEM_XW_BYTES);
    cudaFuncSetAttribute(rnn_cluster_kernel,
                         cudaFuncAttributeMaxDynamicSharedMemorySize, SMEM_MAIN_BYTES);

    dim3 gxw(TSZ / TT, BSZ / 4);
    xw_kernel<<<gxw, NTHRX, SMEM_XW_BYTES>>>(x, Wx, brnn);
    rnn_cluster_kernel<<<NCTA, NTHR, SMEM_MAIN_BYTES>>>(Wh, Wd, bd, out);
}

// round 16
// speedup vs baseline: 1.2447x; 1.2447x over previous
#include <cuda_runtime.h>
#include <cstdint>

// RNN: B=512, T=512, D=64, H=512, O=1
// R10: 4-CTA cluster k-split. 32 clusters x 4 CTAs (128 CTAs, 512 thr).
//  CTA rank q owns k-quarter & j-quarter [128q,128q+128); cluster owns 16
//  batch rows. Thread j's strided across quarters (j = lq + 128c) so each
//  acc quad maps to one dest CTA -> coalesced DSMEM pushes. 56/128 W_h rows
//  cached in SMEM, 72 streamed (L2 traffic 18MB/step, was 48MB).
//  2 k-groups x 2 row-groups intra-CTA; kg1 -> kg0 via smem scratch.
//  xw precomputed to [T][H][B] scratch for vectorized final-phase loads.

#define BSZ 512
#define TSZ 512
#define DSZ 64
#define HSZ 512
#define NTHR 512
#define NCTA 128
#define CSZ  4        // cluster size
#define KQ   128      // k-rows per CTA (quarter)
#define KGL  64       // k-rows per kg group
#define KCG  28       // cached rows per kg group (56/CTA)
#define UPF  6        // (64-28)=36, 36%6==0
#define CROWS 16      // batch rows per cluster

// smem floats: whc 2*28*512=28672 | hsm 128*16=2048 | xbf 16384 | red 8192 | wd 512
#define SMEM_MAIN_BYTES ((2*KCG*HSZ + KQ*16 + 2*4*4*128*4 + 2*4*2*128*4 + 512) * 4)

#define TT 16
#define NTHRX 256
#define SMEM_XW_BYTES ((DSZ * HSZ + TT * DSZ * 4) * 4)

__device__ float g_xw[(size_t)TSZ * HSZ * BSZ];   // [T][H][B]

typedef unsigned long long u64;

__device__ __forceinline__ void ffma2(u64& acc, u64 a, u64 b) {
    asm("fma.rn.f32x2 %0, %1, %2, %0;" : "+l"(acc) : "l"(a), "l"(b));
}
__device__ __forceinline__ u64 pack2(float lo, float hi) {
    u64 r; asm("mov.b64 %0, {%1, %2};" : "=l"(r) : "f"(lo), "f"(hi)); return r;
}
__device__ __forceinline__ void unpack2(float& lo, float& hi, u64 v) {
    asm("mov.b64 {%0, %1}, %2;" : "=f"(lo), "=f"(hi) : "l"(v));
}
__device__ __forceinline__ float4 u64pair_f4(u64 a, u64 b) {
    float4 v;
    unpack2(v.x, v.y, a);
    unpack2(v.z, v.w, b);
    return v;
}
__device__ __forceinline__ uint32_t smem_u32(const void* p) {
    uint32_t a;
    asm("{ .reg .u64 t; cvta.to.shared.u64 t, %1; cvt.u32.u64 %0, t; }"
        : "=r"(a) : "l"(p));
    return a;
}
__device__ __forceinline__ uint32_t mapa_rank(uint32_t addr, uint32_t r) {
    uint32_t o;
    asm("mapa.shared::cluster.u32 %0, %1, %2;" : "=r"(o) : "r"(addr), "r"(r));
    return o;
}
__device__ __forceinline__ void st_cluster_f4(uint32_t a, float4 v) {
    asm volatile("st.shared::cluster.v4.f32 [%0], {%1,%2,%3,%4};"
                 :: "r"(a), "f"(v.x), "f"(v.y), "f"(v.z), "f"(v.w) : "memory");
}
__device__ __forceinline__ void st_cluster_f32(uint32_t a, float v) {
    asm volatile("st.shared::cluster.f32 [%0], %1;" :: "r"(a), "f"(v) : "memory");
}
#define CLUSTER_SYNC() do { \
    asm volatile("barrier.cluster.arrive.aligned;" ::: "memory"); \
    asm volatile("barrier.cluster.wait.aligned;"   ::: "memory"); \
} while (0)

// one k-step: F[c][0..3] += {w_c,w_c} * h row-pairs (8 rows of this rg)
__device__ __forceinline__ void kbody(u64 F[4][4], const float w[4], const float* hb) {
    ulonglong2 hA = *reinterpret_cast<const ulonglong2*>(hb);
    ulonglong2 hB = *reinterpret_cast<const ulonglong2*>(hb + 4);
    #pragma unroll
    for (int c = 0; c < 4; c++) {
        u64 wp = pack2(w[c], w[c]);
        ffma2(F[c][0], wp, hA.x);
        ffma2(F[c][1], wp, hA.y);
        ffma2(F[c][2], wp, hB.x);
        ffma2(F[c][3], wp, hB.y);
    }
}

// ---------------------------------------------------------------------------
// Kernel 1: XW = x @ W_x + b_rnn  ->  g_xw[T][H][B]
// ---------------------------------------------------------------------------
__global__ __launch_bounds__(NTHRX, 1)
void xw_kernel(const float* __restrict__ x,
               const float* __restrict__ Wx,
               const float* __restrict__ brnn)
{
    extern __shared__ float smem[];
    float* wx_s = smem;                  // [64][512]
    float* xs   = wx_s + DSZ * HSZ;      // [TT][64][4]

    const int tid = threadIdx.x;
    const int t0  = blockIdx.x * TT;
    const int b0  = blockIdx.y * 4;

    {
        const float4* g = reinterpret_cast<const float4*>(Wx);
        float4* d = reinterpret_cast<float4*>(wx_s);
        #pragma unroll 8
        for (int i = tid; i < DSZ * HSZ / 4; i += NTHRX) d[i] = g[i];
    }
    #pragma unroll
    for (int i = 0; i < TT * DSZ * 4 / NTHRX; i++) {
        int idx = tid + i * NTHRX;
        int d = idx & 63;
        int t = (idx >> 6) & (TT - 1);
        int r = idx >> 10;
        xs[(t * DSZ + d) * 4 + r] = x[((size_t)(b0 + r) * TSZ + t0 + t) * DSZ + d];
    }
    __syncthreads();

    const float2* wx2 = reinterpret_cast<const float2*>(wx_s) + tid;
    float bA = brnn[2 * tid], bB = brnn[2 * tid + 1];
    u64 bA2 = pack2(bA, bA), bB2 = pack2(bB, bB);

    for (int t = 0; t < TT; t++) {
        u64 a01 = bA2, a23 = bA2, c01 = bB2, c23 = bB2;
        const ulonglong2* xv = reinterpret_cast<const ulonglong2*>(xs + t * DSZ * 4);
        #pragma unroll 8
        for (int k = 0; k < DSZ; k++) {
            float2 w = wx2[k * (HSZ / 2)];
            ulonglong2 hv = xv[k];
            u64 wA = pack2(w.x, w.x);
            u64 wB = pack2(w.y, w.y);
            ffma2(a01, wA, hv.x);
            ffma2(a23, wA, hv.y);
            ffma2(c01, wB, hv.x);
            ffma2(c23, wB, hv.y);
        }
        // store [T][H][B]: row j=2tid(+1), 4 batch entries contiguous
        float4 va = u64pair_f4(a01, a23);
        float4 vb = u64pair_f4(c01, c23);
        size_t base = ((size_t)(t0 + t) * HSZ + 2 * tid) * BSZ + b0;
        *reinterpret_cast<float4*>(g_xw + base)       = va;
        *reinterpret_cast<float4*>(g_xw + base + BSZ) = vb;
    }
}

// ---------------------------------------------------------------------------
// Kernel 2: 4-CTA clustered persistent recurrence.
// ---------------------------------------------------------------------------
__global__ __launch_bounds__(NTHR, 1) __cluster_dims__(CSZ, 1, 1)
void rnn_cluster_kernel(const float* __restrict__ Wh,
                        const float* __restrict__ Wd,
                        const float* __restrict__ bd,
                        float* __restrict__ out)
{
    extern __shared__ float smem[];
    float*  whc  = smem;                                     // [2][KCG][512]
    float*  hsm  = whc + 2 * KCG * HSZ;                      // [128][16]
    float4* xbf4 = reinterpret_cast<float4*>(hsm + KQ * 16); // [2][4s][4rs][128]
    float4* red4 = xbf4 + 2 * 4 * 4 * 128;                   // [2rg][4c][2h][128]
    float*  wd_s = reinterpret_cast<float*>(red4 + 2 * 4 * 2 * 128);  // [512]

    const int tid = threadIdx.x;
    uint32_t rank;
    asm("mov.u32 %0, %%cluster_ctarank;" : "=r"(rank));
    const int b0c = (blockIdx.x >> 2) * CROWS;
    const int kg  = tid >> 8;           // k-group 0/1
    const int rg  = (tid >> 7) & 1;     // row-group 0/1 (rows 8rg..8rg+7)
    const int lq  = tid & 127;          // j = lq + 128c
    const int jlF = tid >> 2;           // final-phase j-local
    const int rqF = tid & 3;            // final-phase row-quad

    // ---- preload cached W_h rows (both kg groups) and W_d ----
    {
        #pragma unroll
        for (int gg = 0; gg < 2; gg++) {
            const float4* src = reinterpret_cast<const float4*>(
                Wh + ((size_t)rank * KQ + gg * KGL) * HSZ);
            float4* dst = reinterpret_cast<float4*>(whc + gg * KCG * HSZ);
            for (int i = tid; i < KCG * HSZ / 4; i += NTHR) dst[i] = src[i];
        }
        wd_s[tid] = Wd[tid];
    }
    __syncthreads();

    const float* wc = whc + kg * KCG * HSZ + lq;                       // cached
    const float* ws = Wh + ((size_t)(rank * KQ + kg * KGL + KCG)) * HSZ + lq;  // streamed
    const uint32_t xb_base = smem_u32(xbf4);
    const uint32_t rd_base = smem_u32(red4);

    for (int t = 0; t < TSZ; t++) {
        const int p = t & 1;

        u64 F[4][4];
        #pragma unroll
        for (int c = 0; c < 4; c++)
            #pragma unroll
            for (int j = 0; j < 4; j++) F[c][j] = 0ull;

        if (t > 0) {
            // ---- cached rows ----
            #pragma unroll 4
            for (int k = 0; k < KCG; k++) {
                float w[4];
                #pragma unroll
                for (int c = 0; c < 4; c++) w[c] = wc[k * HSZ + 128 * c];
                kbody(F, w, hsm + (kg * KGL + k) * 16 + rg * 8);
            }
            // ---- streamed rows, UPF-deep rotating prefetch ----
            float wreg[UPF][4];
            #pragma unroll
            for (int u = 0; u < UPF; u++)
                #pragma unroll
                for (int c = 0; c < 4; c++)
                    wreg[u][c] = ws[(size_t)u * HSZ + 128 * c];

            for (int kb = KCG; kb < KGL; kb += UPF) {
                #pragma unroll
                for (int u = 0; u < UPF; u++) {
                    float w[4];
                    #pragma unroll
                    for (int c = 0; c < 4; c++) w[c] = wreg[u][c];
                    if (kb + UPF < KGL) {
                        #pragma unroll
                        for (int c = 0; c < 4; c++)
                            wreg[u][c] = ws[(size_t)(kb - KCG + UPF + u) * HSZ + 128 * c];
                    }
                    kbody(F, w, hsm + (kg * KGL + kb + u) * 16 + rg * 8);
                }
            }
        }

        // prefetch xw for final phase (overlaps tail latency)
        float4 xr = *reinterpret_cast<const float4*>(
            g_xw + ((size_t)t * HSZ + rank * KQ + jlF) * BSZ + b0c + 4 * rqF);

        // ---- kg1 -> scratch ----
        if (kg == 1) {
            #pragma unroll
            for (int c = 0; c < 4; c++)
                #pragma unroll
                for (int h = 0; h < 2; h++)
                    red4[((rg * 4 + c) * 2 + h) * 128 + lq] =
                        u64pair_f4(F[c][2 * h], F[c][2 * h + 1]);
        }
        __syncthreads();   // S1: red visible; all hsm reads drained

        // ---- kg0: add scratch, push quarter c to CTA c ----
        if (kg == 0) {
            #pragma unroll
            for (int c = 0; c < 4; c++) {
                #pragma unroll
                for (int h = 0; h < 2; h++) {
                    float4 f = u64pair_f4(F[c][2 * h], F[c][2 * h + 1]);
                    float4 q = red4[((rg * 4 + c) * 2 + h) * 128 + lq];
                    f.x += q.x; f.y += q.y; f.z += q.z; f.w += q.w;
                    // xbf[p][sender=rank][rslot=2rg+h][jl=lq]
                    uint32_t off = (uint32_t)((((p * 4 + rank) * 4 + (2 * rg + h)) * 128 + lq) * 16);
                    st_cluster_f4(mapa_rank(xb_base + off, (uint32_t)c), f);
                }
            }
        }

        CLUSTER_SYNC();   // all pushes delivered cluster-wide

        // ---- final: sum 4 senders + xw, relu, store h ----
        {
            float4 f = xr;
            #pragma unroll
            for (int s = 0; s < 4; s++) {
                float4 q = xbf4[((p * 4 + s) * 4 + rqF) * 128 + jlF];
                f.x += q.x; f.y += q.y; f.z += q.z; f.w += q.w;
            }
            f.x = fmaxf(f.x, 0.f);
            f.y = fmaxf(f.y, 0.f);
            f.z = fmaxf(f.z, 0.f);
            f.w = fmaxf(f.w, 0.f);
            *reinterpret_cast<float4*>(hsm + jlF * 16 + 4 * rqF) = f;
        }
        __syncthreads();   // S2: h_t visible CTA-wide
    }

    // ---- final dense: out[b] = relu(h_T[b,:] @ W_d + b_d) ----
    {
        const int wr = tid >> 5;      // warp 0..15 -> batch row
        const int l  = tid & 31;
        float s = 0.f;
        #pragma unroll
        for (int i = 0; i < 4; i++) {
            int jl = l + 32 * i;
            s += hsm[jl * 16 + wr] * wd_s[rank * KQ + jl];
        }
        #pragma unroll
        for (int off = 16; off > 0; off >>= 1)
            s += __shfl_xor_sync(0xffffffffu, s, off);
        if (l == 0)   // push partial (incl. rank 0 to itself)
            st_cluster_f32(mapa_rank(rd_base + (uint32_t)(rank * 16 + wr) * 4, 0u), s);
        CLUSTER_SYNC();
        if (rank == 0 && tid < CROWS) {
            const float* rf = reinterpret_cast<const float*>(red4);
            float sum = rf[tid] + rf[16 + tid] + rf[32 + tid] + rf[48 + tid];
            out[b0c + tid] = fmaxf(sum + bd[0], 0.f);
        }
        CLUSTER_SYNC();   // keep smem alive until rank0 reads complete
    }
}

extern "C" void kernel_launch(void* const* d_in, const int* in_sizes, int n_in,
                              void* d_out, int out_size) {
    const float* x    = (const float*)d_in[0];
    const float* Wx   = (const float*)d_in[1];
    const float* Wh   = (const float*)d_in[2];
    const float* brnn = (const float*)d_in[3];
    const float* Wd   = (const float*)d_in[4];
    const float* bd   = (const float*)d_in[5];
    float* out = (float*)d_out;

    cudaFuncSetAttribute(xw_kernel,
                         cudaFuncAttributeMaxDynamicSharedMemorySize, SMEM_XW_BYTES);
    cudaFuncSetAttribute(rnn_cluster_kernel,
                         cudaFuncAttributeMaxDynamicSharedMemorySize, SMEM_MAIN_BYTES);

    dim3 gxw(TSZ / TT, BSZ / 4);
    xw_kernel<<<gxw, NTHRX, SMEM_XW_BYTES>>>(x, Wx, brnn);
    rnn_cluster_kernel<<<NCTA, NTHR, SMEM_MAIN_BYTES>>>(Wh, Wd, bd, out);
}

// round 17
// speedup vs baseline: 1.3100x; 1.0525x over previous
#include <cuda_runtime.h>
#include <cstdint>

// RNN: B=512, T=512, D=64, H=512, O=1
// R11 = R10 + W_h repack: g_whp[k][lq*4+c] = Wh[k][lq+128c], so each thread's
// 4 w-values are one LDG.128/LDS.128 (k-loop L1 wavefronts 6 -> 3 per warp/k).
// Everything else identical to R10 (4-CTA cluster k-split, 32x4 CTAs, 512 thr).

#define BSZ 512
#define TSZ 512
#define DSZ 64
#define HSZ 512
#define NTHR 512
#define NCTA 128
#define CSZ  4        // cluster size
#define KQ   128      // k-rows per CTA (quarter)
#define KGL  64       // k-rows per kg group
#define KCG  28       // cached rows per kg group (56/CTA)
#define UPF  6        // (64-28)=36, 36%6==0
#define CROWS 16      // batch rows per cluster

// smem floats: whc 2*28*512=28672 | hsm 128*16=2048 | xbf 16384 | red 8192 | wd 512
#define SMEM_MAIN_BYTES ((2*KCG*HSZ + KQ*16 + 2*4*4*128*4 + 2*4*2*128*4 + 512) * 4)

#define TT 16
#define NTHRX 256
#define SMEM_XW_BYTES ((DSZ * HSZ + TT * DSZ * 4) * 4)

__device__ float g_xw[(size_t)TSZ * HSZ * BSZ];   // [T][H][B]
__device__ float g_whp[(size_t)HSZ * HSZ];        // permuted W_h

typedef unsigned long long u64;

__device__ __forceinline__ void ffma2(u64& acc, u64 a, u64 b) {
    asm("fma.rn.f32x2 %0, %1, %2, %0;" : "+l"(acc) : "l"(a), "l"(b));
}
__device__ __forceinline__ u64 pack2(float lo, float hi) {
    u64 r; asm("mov.b64 %0, {%1, %2};" : "=l"(r) : "f"(lo), "f"(hi)); return r;
}
__device__ __forceinline__ void unpack2(float& lo, float& hi, u64 v) {
    asm("mov.b64 {%0, %1}, %2;" : "=f"(lo), "=f"(hi) : "l"(v));
}
__device__ __forceinline__ float4 u64pair_f4(u64 a, u64 b) {
    float4 v;
    unpack2(v.x, v.y, a);
    unpack2(v.z, v.w, b);
    return v;
}
__device__ __forceinline__ uint32_t smem_u32(const void* p) {
    uint32_t a;
    asm("{ .reg .u64 t; cvta.to.shared.u64 t, %1; cvt.u32.u64 %0, t; }"
        : "=r"(a) : "l"(p));
    return a;
}
__device__ __forceinline__ uint32_t mapa_rank(uint32_t addr, uint32_t r) {
    uint32_t o;
    asm("mapa.shared::cluster.u32 %0, %1, %2;" : "=r"(o) : "r"(addr), "r"(r));
    return o;
}
__device__ __forceinline__ void st_cluster_f4(uint32_t a, float4 v) {
    asm volatile("st.shared::cluster.v4.f32 [%0], {%1,%2,%3,%4};"
                 :: "r"(a), "f"(v.x), "f"(v.y), "f"(v.z), "f"(v.w) : "memory");
}
__device__ __forceinline__ void st_cluster_f32(uint32_t a, float v) {
    asm volatile("st.shared::cluster.f32 [%0], %1;" :: "r"(a), "f"(v) : "memory");
}
#define CLUSTER_SYNC() do { \
    asm volatile("barrier.cluster.arrive.aligned;" ::: "memory"); \
    asm volatile("barrier.cluster.wait.aligned;"   ::: "memory"); \
} while (0)

// one k-step: F[c][0..3] += {w_c,w_c} * h row-pairs (8 rows of this rg)
__device__ __forceinline__ void kbody(u64 F[4][4], float4 w, const float* hb) {
    ulonglong2 hA = *reinterpret_cast<const ulonglong2*>(hb);
    ulonglong2 hB = *reinterpret_cast<const ulonglong2*>(hb + 4);
    const float wv[4] = {w.x, w.y, w.z, w.w};
    #pragma unroll
    for (int c = 0; c < 4; c++) {
        u64 wp = pack2(wv[c], wv[c]);
        ffma2(F[c][0], wp, hA.x);
        ffma2(F[c][1], wp, hA.y);
        ffma2(F[c][2], wp, hB.x);
        ffma2(F[c][3], wp, hB.y);
    }
}

// ---------------------------------------------------------------------------
// Kernel 0: repack W_h -> g_whp[k][lq*4+c] = Wh[k][lq+128c]
// ---------------------------------------------------------------------------
__global__ __launch_bounds__(256, 1)
void repack_kernel(const float* __restrict__ Wh)
{
    int d = blockIdx.x * 256 + threadIdx.x;   // grid covers 512*512
    #pragma unroll 4
    for (int i = 0; i < 4; i++, d += gridDim.x * 256) {
        int k = d >> 9;
        int r = d & 511;
        int lq = r >> 2;
        int c  = r & 3;
        g_whp[d] = Wh[k * HSZ + lq + 128 * c];
    }
}

// ---------------------------------------------------------------------------
// Kernel 1: XW = x @ W_x + b_rnn  ->  g_xw[T][H][B]
// ---------------------------------------------------------------------------
__global__ __launch_bounds__(NTHRX, 1)
void xw_kernel(const float* __restrict__ x,
               const float* __restrict__ Wx,
               const float* __restrict__ brnn)
{
    extern __shared__ float smem[];
    float* wx_s = smem;                  // [64][512]
    float* xs   = wx_s + DSZ * HSZ;      // [TT][64][4]

    const int tid = threadIdx.x;
    const int t0  = blockIdx.x * TT;
    const int b0  = blockIdx.y * 4;

    {
        const float4* g = reinterpret_cast<const float4*>(Wx);
        float4* d = reinterpret_cast<float4*>(wx_s);
        #pragma unroll 8
        for (int i = tid; i < DSZ * HSZ / 4; i += NTHRX) d[i] = g[i];
    }
    #pragma unroll
    for (int i = 0; i < TT * DSZ * 4 / NTHRX; i++) {
        int idx = tid + i * NTHRX;
        int d = idx & 63;
        int t = (idx >> 6) & (TT - 1);
        int r = idx >> 10;
        xs[(t * DSZ + d) * 4 + r] = x[((size_t)(b0 + r) * TSZ + t0 + t) * DSZ + d];
    }
    __syncthreads();

    const float2* wx2 = reinterpret_cast<const float2*>(wx_s) + tid;
    float bA = brnn[2 * tid], bB = brnn[2 * tid + 1];
    u64 bA2 = pack2(bA, bA), bB2 = pack2(bB, bB);

    for (int t = 0; t < TT; t++) {
        u64 a01 = bA2, a23 = bA2, c01 = bB2, c23 = bB2;
        const ulonglong2* xv = reinterpret_cast<const ulonglong2*>(xs + t * DSZ * 4);
        #pragma unroll 8
        for (int k = 0; k < DSZ; k++) {
            float2 w = wx2[k * (HSZ / 2)];
            ulonglong2 hv = xv[k];
            u64 wA = pack2(w.x, w.x);
            u64 wB = pack2(w.y, w.y);
            ffma2(a01, wA, hv.x);
            ffma2(a23, wA, hv.y);
            ffma2(c01, wB, hv.x);
            ffma2(c23, wB, hv.y);
        }
        float4 va = u64pair_f4(a01, a23);
        float4 vb = u64pair_f4(c01, c23);
        size_t base = ((size_t)(t0 + t) * HSZ + 2 * tid) * BSZ + b0;
        *reinterpret_cast<float4*>(g_xw + base)       = va;
        *reinterpret_cast<float4*>(g_xw + base + BSZ) = vb;
    }
}

// ---------------------------------------------------------------------------
// Kernel 2: 4-CTA clustered persistent recurrence.
// ---------------------------------------------------------------------------
__global__ __launch_bounds__(NTHR, 1) __cluster_dims__(CSZ, 1, 1)
void rnn_cluster_kernel(const float* __restrict__ Wd,
                        const float* __restrict__ bd,
                        float* __restrict__ out)
{
    extern __shared__ float smem[];
    float*  whc  = smem;                                     // [2][KCG][512] (permuted)
    float*  hsm  = whc + 2 * KCG * HSZ;                      // [128][16]
    float4* xbf4 = reinterpret_cast<float4*>(hsm + KQ * 16); // [2][4s][4rs][128]
    float4* red4 = xbf4 + 2 * 4 * 4 * 128;                   // [2rg][4c][2h][128]
    float*  wd_s = reinterpret_cast<float*>(red4 + 2 * 4 * 2 * 128);  // [512]

    const int tid = threadIdx.x;
    uint32_t rank;
    asm("mov.u32 %0, %%cluster_ctarank;" : "=r"(rank));
    const int b0c = (blockIdx.x >> 2) * CROWS;
    const int kg  = tid >> 8;           // k-group 0/1
    const int rg  = (tid >> 7) & 1;     // row-group 0/1 (rows 8rg..8rg+7)
    const int lq  = tid & 127;          // j = lq + 128c
    const int jlF = tid >> 2;           // final-phase j-local
    const int rqF = tid & 3;            // final-phase row-quad

    // ---- preload cached permuted W_h rows and W_d ----
    {
        #pragma unroll
        for (int gg = 0; gg < 2; gg++) {
            const float4* src = reinterpret_cast<const float4*>(
                g_whp + ((size_t)rank * KQ + gg * KGL) * HSZ);
            float4* dst = reinterpret_cast<float4*>(whc + gg * KCG * HSZ);
            for (int i = tid; i < KCG * HSZ / 4; i += NTHR) dst[i] = src[i];
        }
        wd_s[tid] = Wd[tid];
    }
    __syncthreads();

    const float4* wc4 = reinterpret_cast<const float4*>(whc + kg * KCG * HSZ) + lq;
    const float4* ws4 = reinterpret_cast<const float4*>(
        g_whp + ((size_t)(rank * KQ + kg * KGL + KCG)) * HSZ) + lq;
    const uint32_t xb_base = smem_u32(xbf4);
    const uint32_t rd_base = smem_u32(red4);

    for (int t = 0; t < TSZ; t++) {
        const int p = t & 1;

        u64 F[4][4];
        #pragma unroll
        for (int c = 0; c < 4; c++)
            #pragma unroll
            for (int j = 0; j < 4; j++) F[c][j] = 0ull;

        if (t > 0) {
            // ---- cached rows (one LDS.128 per k) ----
            #pragma unroll 4
            for (int k = 0; k < KCG; k++)
                kbody(F, wc4[k * (HSZ / 4)], hsm + (kg * KGL + k) * 16 + rg * 8);

            // ---- streamed rows (one LDG.128 per k), UPF-deep prefetch ----
            float4 wreg[UPF];
            #pragma unroll
            for (int u = 0; u < UPF; u++)
                wreg[u] = ws4[u * (HSZ / 4)];

            for (int kb = KCG; kb < KGL; kb += UPF) {
                #pragma unroll
                for (int u = 0; u < UPF; u++) {
                    float4 w = wreg[u];
                    if (kb + UPF < KGL)
                        wreg[u] = ws4[(size_t)(kb - KCG + UPF + u) * (HSZ / 4)];
                    kbody(F, w, hsm + (kg * KGL + kb + u) * 16 + rg * 8);
                }
            }
        }

        // prefetch xw for final phase (overlaps tail latency)
        float4 xr = *reinterpret_cast<const float4*>(
            g_xw + ((size_t)t * HSZ + rank * KQ + jlF) * BSZ + b0c + 4 * rqF);

        // ---- kg1 -> scratch ----
        if (kg == 1) {
            #pragma unroll
            for (int c = 0; c < 4; c++)
                #pragma unroll
                for (int h = 0; h < 2; h++)
                    red4[((rg * 4 + c) * 2 + h) * 128 + lq] =
                        u64pair_f4(F[c][2 * h], F[c][2 * h + 1]);
        }
        __syncthreads();   // S1: red visible; all hsm reads drained

        // ---- kg0: add scratch, push quarter c to CTA c ----
        if (kg == 0) {
            #pragma unroll
            for (int c = 0; c < 4; c++) {
                #pragma unroll
                for (int h = 0; h < 2; h++) {
                    float4 f = u64pair_f4(F[c][2 * h], F[c][2 * h + 1]);
                    float4 q = red4[((rg * 4 + c) * 2 + h) * 128 + lq];
                    f.x += q.x; f.y += q.y; f.z += q.z; f.w += q.w;
                    uint32_t off = (uint32_t)((((p * 4 + rank) * 4 + (2 * rg + h)) * 128 + lq) * 16);
                    st_cluster_f4(mapa_rank(xb_base + off, (uint32_t)c), f);
                }
            }
        }

        CLUSTER_SYNC();   // all pushes delivered cluster-wide

        // ---- final: sum 4 senders + xw, relu, store h ----
        {
            float4 f = xr;
            #pragma unroll
            for (int s = 0; s < 4; s++) {
                float4 q = xbf4[((p * 4 + s) * 4 + rqF) * 128 + jlF];
                f.x += q.x; f.y += q.y; f.z += q.z; f.w += q.w;
            }
            f.x = fmaxf(f.x, 0.f);
            f.y = fmaxf(f.y, 0.f);
            f.z = fmaxf(f.z, 0.f);
            f.w = fmaxf(f.w, 0.f);
            *reinterpret_cast<float4*>(hsm + jlF * 16 + 4 * rqF) = f;
        }
        __syncthreads();   // S2: h_t visible CTA-wide
    }

    // ---- final dense: out[b] = relu(h_T[b,:] @ W_d + b_d) ----
    {
        const int wr = tid >> 5;      // warp 0..15 -> batch row
        const int l  = tid & 31;
        float s = 0.f;
        #pragma unroll
        for (int i = 0; i < 4; i++) {
            int jl = l + 32 * i;
            s += hsm[jl * 16 + wr] * wd_s[rank * KQ + jl];
        }
        #pragma unroll
        for (int off = 16; off > 0; off >>= 1)
            s += __shfl_xor_sync(0xffffffffu, s, off);
        if (l == 0)
            st_cluster_f32(mapa_rank(rd_base + (uint32_t)(rank * 16 + wr) * 4, 0u), s);
        CLUSTER_SYNC();
        if (rank == 0 && tid < CROWS) {
            const float* rf = reinterpret_cast<const float*>(red4);
            float sum = rf[tid] + rf[16 + tid] + rf[32 + tid] + rf[48 + tid];
            out[b0c + tid] = fmaxf(sum + bd[0], 0.f);
        }
        CLUSTER_SYNC();   // keep smem alive until rank0 reads complete
    }
}

extern "C" void kernel_launch(void* const* d_in, const int* in_sizes, int n_in,
                              void* d_out, int out_size) {
    const float* x    = (const float*)d_in[0];
    const float* Wx   = (const float*)d_in[1];
    const float* Wh   = (const float*)d_in[2];
    const float* brnn = (const float*)d_in[3];
    const float* Wd   = (const float*)d_in[4];
    const float* bd   = (const float*)d_in[5];
    float* out = (float*)d_out;

    cudaFuncSetAttribute(xw_kernel,
                         cudaFuncAttributeMaxDynamicSharedMemorySize, SMEM_XW_BYTES);
    cudaFuncSetAttribute(rnn_cluster_kernel,
                         cudaFuncAttributeMaxDynamicSharedMemorySize, SMEM_MAIN_BYTES);

    repack_kernel<<<HSZ * HSZ / (256 * 4), 256>>>(Wh);
    dim3 gxw(TSZ / TT, BSZ / 4);
    xw_kernel<<<gxw, NTHRX, SMEM_XW_BYTES>>>(x, Wx, brnn);
    rnn_cluster_kernel<<<NCTA, NTHR, SMEM_MAIN_BYTES>>>(Wd, bd, out);
}